// round 12
// baseline (speedup 1.0000x reference)
#include <cuda_runtime.h>
#include <stdint.h>

// ============================================================================
// JMEFairnessLoss — SINGLE kernel:
//   phase A: threshold top-100 gather on pred (exact radix fallback);
//            gumbel RNG hoisted into the load/barrier shadow
//   phase B: gumbel soft-rank exposure, f32 tanh (MUFU wall ~23us),
//            truth loads interleaved under the tanh shadow
//   rank-by-count with dynamic bound (s_cnt ~158)
//   epilogue: fixed-point integer atomics (deterministic) + last-block
//             ticket finalize -> (total, ii, gg); accumulators self-reset.
// ============================================================================

namespace jme {
constexpr int B      = 1024;
constexpr int NITEMS = 10000;
constexpr int TOPK   = 100;
constexpr int NS     = 10;
constexpr int NIG    = 16;
constexpr int NPAIR  = 128;
constexpr int NTASK  = NS * TOPK;     // 1000
constexpr int CAND   = 256;
}

// ---- global accumulators (all raw sums are >= 0; fixed-point, exact) ------
__device__ unsigned long long g_pairD[jme::NPAIR];   // sum e  * 2^32 per (ug,ig)
__device__ unsigned int       g_pairC[jme::NPAIR];   // counts (exact ints)
__device__ unsigned long long g_sq;                  // sum e^2 * 2^32
__device__ unsigned long long g_sl;                  // sum e   * 2^32
__device__ unsigned long long g_ts;                  // sum truth * 2^26
__device__ unsigned int       g_done;

// ------------------------------- threefry2x32 (JAX-exact, key=(0,1)) -------
__device__ __forceinline__ void tf_round(uint32_t& x0, uint32_t& x1, int r) {
    x0 += x1;
    x1 = __funnelshift_l(x1, x1, r);
    x1 ^= x0;
}
__device__ __forceinline__ uint2 threefry01(uint32_t x0, uint32_t x1) {
    const uint32_t k0 = 0u, k1 = 1u, k2 = 0x1BD11BDBu;
    x0 += k0; x1 += k1;
    tf_round(x0,x1,13); tf_round(x0,x1,15); tf_round(x0,x1,26); tf_round(x0,x1,6);
    x0 += k1; x1 += k2 + 1u;
    tf_round(x0,x1,17); tf_round(x0,x1,29); tf_round(x0,x1,16); tf_round(x0,x1,24);
    x0 += k2; x1 += k0 + 2u;
    tf_round(x0,x1,13); tf_round(x0,x1,15); tf_round(x0,x1,26); tf_round(x0,x1,6);
    x0 += k0; x1 += k1 + 3u;
    tf_round(x0,x1,17); tf_round(x0,x1,29); tf_round(x0,x1,16); tf_round(x0,x1,24);
    x0 += k1; x1 += k2 + 4u;
    tf_round(x0,x1,13); tf_round(x0,x1,15); tf_round(x0,x1,26); tf_round(x0,x1,6);
    x0 += k2; x1 += k0 + 5u;
    return make_uint2(x0, x1);
}
__device__ __forceinline__ float gumbel_at(int lin) {
    uint2 r = threefry01(0u, (uint32_t)lin);
    uint32_t bits = r.x ^ r.y;
    float f = __uint_as_float((bits >> 9) | 0x3F800000u) - 1.0f;
    float u = fmaxf(1.17549435e-38f, f);
    return -__logf(-__logf(u));
}

// ------------------------------- key helpers -------------------------------
__device__ __forceinline__ uint32_t f2key(float f) {
    uint32_t u = __float_as_uint(f);
    return (u & 0x80000000u) ? ~u : (u | 0x80000000u);
}
__device__ __forceinline__ float key2f(uint32_t k) {
    uint32_t fb = (k & 0x80000000u) ? (k ^ 0x80000000u) : ~k;
    return __uint_as_float(fb);
}

// ------------------------------- the kernel --------------------------------
__global__ __launch_bounds__(256, 7) void k_row(const float* __restrict__ pred,
                                                const float* __restrict__ truth,
                                                const int*   __restrict__ item_groups,
                                                const int*   __restrict__ user_groups,
                                                float* __restrict__ out) {
    __shared__ unsigned long long cand[jme::CAND];   // 2 KB
    __shared__ float sval[jme::TOPK];
    __shared__ int   s_ig[jme::TOPK];
    __shared__ __align__(16) float nz[jme::NS][jme::TOPK];   // noisy * 5
    __shared__ float expo_sb[jme::NTASK];            // aliased: red / hist
    __shared__ __align__(16) float sdelta[jme::TOPK];
    __shared__ int s_cnt;
    __shared__ uint32_t s_prefix;
    __shared__ int s_rem;
    __shared__ int s_ticket;
    float*    red  = expo_sb;                        // reduction alias
    uint32_t* hist = (uint32_t*)expo_sb;             // fallback alias

    const int row = blockIdx.x, tid = threadIdx.x;
    const float4* rp4 = (const float4*)(pred  + (size_t)row * jme::NITEMS);
    const float4* tr4 = (const float4*)(truth + (size_t)row * jme::NITEMS);
    constexpr int N4 = jme::NITEMS / 4;              // 2500

    // task mapping for this thread (4 tasks tk = tid + 256*m, tk < 1000)
    int sI[4], iI[4];
    #pragma unroll
    for (int m = 0; m < 4; ++m) {
        int tk = tid + 256 * m;
        int s = (tk < jme::NTASK) ? (tk / jme::TOPK) : 0;
        sI[m] = s;
        iI[m] = (tk < jme::NTASK) ? (tk - jme::TOPK * s) : 0;
    }

    // =============== phase A: top-100 gather (pred only) ===================
    cand[tid] = 0ULL;
    if (tid == 0) s_cnt = 0;
    __syncthreads();

    const float THR = 2.15f;   // N(0,1): E[count>THR]~158, sd~12.5 (cap 256)
    #pragma unroll 5
    for (int c = tid; c < N4; c += 256) {
        float4 v = rp4[c];
        const float vv[4] = {v.x, v.y, v.z, v.w};
        #pragma unroll
        for (int e = 0; e < 4; ++e) {
            if (vv[e] > THR) {
                int pos = atomicAdd(&s_cnt, 1);
                if (pos < jme::CAND)
                    cand[pos] = (((unsigned long long)f2key(vv[e])) << 32)
                              | (uint32_t)(0xFFFFFFFFu - (uint32_t)(4 * c + e));
            }
        }
    }

    // ---- gumbel RNG in the load/barrier shadow (input-independent) --------
    float g4[4];
    #pragma unroll
    for (int m = 0; m < 4; ++m) {
        int lin = (sI[m] * jme::B + row) * jme::TOPK + iI[m];
        g4[m] = gumbel_at(lin);
    }
    __syncthreads();

    // exact fallback (statistically never taken; correctness for any input)
    if (s_cnt < jme::TOPK || s_cnt > jme::CAND) {
        const float* rp = pred + (size_t)row * jme::NITEMS;
        if (tid == 0) { s_rem = jme::TOPK; s_prefix = 0u; }
        __syncthreads();
        uint32_t prefix = 0u;
        for (int shift = 24; shift >= 0; shift -= 8) {
            hist[tid] = 0u;
            __syncthreads();
            const uint32_t himask = (shift == 24) ? 0u : (0xFFFFFFFFu << (shift + 8));
            for (int i = tid; i < jme::NITEMS; i += 256) {
                uint32_t k = f2key(rp[i]);
                if ((k & himask) == prefix)
                    atomicAdd(&hist[(k >> shift) & 0xFF], 1u);
            }
            __syncthreads();
            if (tid == 0) {
                int cum = 0, sel = 0;
                for (int b = 255; b >= 0; --b) {
                    int h = (int)hist[b];
                    if (cum + h >= s_rem) { sel = b; s_rem -= cum; break; }
                    cum += h;
                }
                s_prefix = prefix | ((uint32_t)sel << shift);
            }
            __syncthreads();
            prefix = s_prefix;
            __syncthreads();
        }
        const uint32_t T = prefix;   // exact 100th-largest key
        cand[tid] = 0ULL;
        if (tid == 0) s_cnt = 0;
        __syncthreads();
        for (int i = tid; i < jme::NITEMS; i += 256) {
            uint32_t k = f2key(rp[i]);
            if (k >= T) {
                int pos = atomicAdd(&s_cnt, 1);
                if (pos < jme::CAND)
                    cand[pos] = (((unsigned long long)k) << 32)
                              | (uint32_t)(0xFFFFFFFFu - (uint32_t)i);
            }
        }
        __syncthreads();
    }

    // rank-by-count over the LIVE candidates only (s_cnt ~158, not 256)
    {
        const int n = (s_cnt < jme::CAND) ? s_cnt : jme::CAND;
        unsigned long long e = cand[tid];
        int r = 0;
        #pragma unroll 8
        for (int j = 0; j < n; ++j) r += (cand[j] > e);
        if (e != 0ULL && r < jme::TOPK) {
            sval[r] = key2f((uint32_t)(e >> 32));
            s_ig[r] = item_groups[0xFFFFFFFFu - (uint32_t)e];
        }
    }
    __syncthreads();

    // =============== phase B: exposure (f32 tanh) + hidden truth loads =====
    #pragma unroll
    for (int m = 0; m < 4; ++m) {
        int tk = tid + 256 * m;
        if (tk < jme::NTASK)
            nz[sI[m]][iI[m]] = (sval[iI[m]] + g4[m]) * 5.0f;
    }
    __syncthreads();

    const float L2G = -0.3219280948873623f;     // log2(0.8)
    float tacc = 0.0f;                          // truth partial (hidden loads)
    #pragma unroll
    for (int m = 0; m < 4; ++m) {
        const int tk = tid + 256 * m;

        // ---- issue truth loads for this slice (consumed after tanh loop) --
        float4 p0 = tr4[tid + 256 * m];                      // c <= 1023
        float4 p1 = tr4[tid + 256 * (m + 4)];                // c <= 2047
        float4 p2 = make_float4(0.f, 0.f, 0.f, 0.f);
        if (m < 2) {
            int c2 = tid + 256 * (m + 8);
            if (c2 < N4) p2 = tr4[c2];                       // guard 2500
        }

        // ---- dense f32 tanh task (float4 smem reads) -----------------------
        if (tk < jme::NTASK) {
            const float4* rowp4 = (const float4*)nz[sI[m]];
            const float vi = nz[sI[m]][iI[m]];
            float t0 = 0.0f, t1 = 0.0f, t2 = 0.0f, t3 = 0.0f;
            #pragma unroll 5
            for (int q = 0; q < jme::TOPK / 4; ++q) {
                float4 vj = rowp4[q];
                float a0, a1, a2, a3;
                asm("tanh.approx.f32 %0, %1;" : "=f"(a0) : "f"(vi - vj.x));
                asm("tanh.approx.f32 %0, %1;" : "=f"(a1) : "f"(vi - vj.y));
                asm("tanh.approx.f32 %0, %1;" : "=f"(a2) : "f"(vi - vj.z));
                asm("tanh.approx.f32 %0, %1;" : "=f"(a3) : "f"(vi - vj.w));
                t0 += a0; t1 += a1; t2 += a2; t3 += a3;
            }
            float T = (t0 + t1) + (t2 + t3);
            float ex;
            asm("ex2.approx.f32 %0, %1;" : "=f"(ex)
                : "f"(fmaf(T, 0.5f * L2G, 49.5f * L2G)));
            expo_sb[tk] = ex;
        }

        // ---- consume truth loads (latency long gone) -----------------------
        tacc += ((p0.x + p0.y) + (p0.z + p0.w))
              + ((p1.x + p1.y) + (p1.z + p1.w))
              + ((p2.x + p2.y) + (p2.z + p2.w));
    }
    __syncthreads();

    if (tid < jme::TOPK) {
        float acc = 0.0f;
        #pragma unroll
        for (int s = 0; s < jme::NS; ++s) acc += expo_sb[s * jme::TOPK + tid];
        sdelta[tid] = acc * 0.1f;           // raw e_i (t deferred)
    }
    __syncthreads();

    // truth reduction (expo_sb now reusable as red)
    red[tid] = tacc;
    __syncthreads();
    for (int o = 128; o > 0; o >>= 1) {
        if (tid < o) red[tid] += red[tid + o];
        __syncthreads();
    }
    if (tid == 0)
        atomicAdd(&g_ts, (unsigned long long)__double2ll_rn((double)red[0] * 67108864.0));

    // =============== per-row partials -> global integer atomics ============
    if (tid == 1) {
        const float4* sd4 = (const float4*)sdelta;
        float sq = 0.0f, sl = 0.0f;
        #pragma unroll
        for (int i = 0; i < jme::TOPK / 4; ++i) {
            float4 e = sd4[i];
            sq += e.x * e.x + e.y * e.y + e.z * e.z + e.w * e.w;
            sl += (e.x + e.y) + (e.z + e.w);
        }
        atomicAdd(&g_sq, (unsigned long long)__double2ll_rn((double)sq * 4294967296.0));
        atomicAdd(&g_sl, (unsigned long long)__double2ll_rn((double)sl * 4294967296.0));
    }
    if (tid >= 32 && tid < 32 + jme::NIG) {
        const int g = tid - 32;
        float sD = 0.0f, c = 0.0f;
        for (int i = 0; i < jme::TOPK; ++i)
            if (s_ig[i] == g) { sD += sdelta[i]; c += 1.0f; }
        const int ug = user_groups[row];
        atomicAdd(&g_pairD[ug * jme::NIG + g],
                  (unsigned long long)__double2ll_rn((double)sD * 4294967296.0));
        atomicAdd(&g_pairC[ug * jme::NIG + g], (unsigned int)c);
    }

    // =============== last-block ticket: finalize ============================
    __threadfence();
    __syncthreads();
    if (tid == 0) s_ticket = (int)atomicAdd(&g_done, 1u);
    __syncthreads();
    if (s_ticket == jme::B - 1) {
        const double t = (double)(long long)__ldcg((const long long*)&g_ts)
                         / 67108864.0 / (double)(jme::B * jme::NITEMS);
        float a2 = 0.0f;
        if (tid < jme::NPAIR) {
            double D = (double)(long long)__ldcg((const long long*)&g_pairD[tid])
                       / 4294967296.0;
            double C = (double)__ldcg((const unsigned int*)&g_pairC[tid]);
            double avg = (C > 0.0) ? ((D - t * C) / fmax(C, 1.0)) : 0.0;
            a2 = (float)(avg * avg);
        }
        red[tid] = a2;
        __syncthreads();
        for (int o = 128; o > 0; o >>= 1) {
            if (tid < o) red[tid] += red[tid + o];
            __syncthreads();
        }
        if (tid == 0) {
            const double BK = (double)(jme::B * jme::TOPK);
            double Sq = (double)(long long)__ldcg((const long long*)&g_sq) / 4294967296.0;
            double Sl = (double)(long long)__ldcg((const long long*)&g_sl) / 4294967296.0;
            const float ii = (float)((Sq - 2.0 * t * Sl + BK * t * t) / BK);
            const float gg = red[0] / (float)jme::NPAIR;
            out[0] = ii + gg;
            out[1] = ii;
            out[2] = gg;
        }
        // reset accumulators for next graph replay
        if (tid < jme::NPAIR) {
            atomicExch(&g_pairD[tid], 0ULL);
            atomicExch(&g_pairC[tid], 0u);
        }
        if (tid == 0) {
            atomicExch(&g_sq, 0ULL);
            atomicExch(&g_sl, 0ULL);
            atomicExch(&g_ts, 0ULL);
            atomicExch(&g_done, 0u);
        }
    }
}

// ------------------------------- launch ------------------------------------
extern "C" void kernel_launch(void* const* d_in, const int* in_sizes, int n_in,
                              void* d_out, int out_size) {
    const float* pred  = (const float*)d_in[0];
    const float* truth = (const float*)d_in[1];
    const int*   ug    = (const int*)  d_in[2];
    const int*   ig    = (const int*)  d_in[3];
    float* out = (float*)d_out;

    k_row<<<jme::B, 256>>>(pred, truth, ig, ug, out);
}

// round 13
// speedup vs baseline: 1.0056x; 1.0056x over previous
#include <cuda_runtime.h>
#include <stdint.h>

// ============================================================================
// JMEFairnessLoss — SINGLE kernel:
//   phase A: threshold top-100 gather on pred (fmax-prefiltered; exact radix
//            fallback); gumbel RNG hoisted into the load/barrier shadow
//   phase B: gumbel soft-rank exposure, f32 tanh (MUFU wall ~23us),
//            truth loads interleaved under the tanh shadow
//   rank-by-count via LDS.128 pairs, dynamic bound (s_cnt ~158)
//   epilogue: warp-shuffle reductions + fixed-point integer atomics
//             (deterministic) + last-block ticket finalize; self-reset.
// ============================================================================

namespace jme {
constexpr int B      = 1024;
constexpr int NITEMS = 10000;
constexpr int TOPK   = 100;
constexpr int NS     = 10;
constexpr int NIG    = 16;
constexpr int NPAIR  = 128;
constexpr int NTASK  = NS * TOPK;     // 1000
constexpr int CAND   = 256;
}

// ---- global accumulators (all raw sums are >= 0; fixed-point, exact) ------
__device__ unsigned long long g_pairD[jme::NPAIR];   // sum e  * 2^32 per (ug,ig)
__device__ unsigned int       g_pairC[jme::NPAIR];   // counts (exact ints)
__device__ unsigned long long g_sq;                  // sum e^2 * 2^32
__device__ unsigned long long g_sl;                  // sum e   * 2^32
__device__ unsigned long long g_ts;                  // sum truth * 2^26
__device__ unsigned int       g_done;

// ------------------------------- threefry2x32 (JAX-exact, key=(0,1)) -------
__device__ __forceinline__ void tf_round(uint32_t& x0, uint32_t& x1, int r) {
    x0 += x1;
    x1 = __funnelshift_l(x1, x1, r);
    x1 ^= x0;
}
__device__ __forceinline__ uint2 threefry01(uint32_t x0, uint32_t x1) {
    const uint32_t k0 = 0u, k1 = 1u, k2 = 0x1BD11BDBu;
    x0 += k0; x1 += k1;
    tf_round(x0,x1,13); tf_round(x0,x1,15); tf_round(x0,x1,26); tf_round(x0,x1,6);
    x0 += k1; x1 += k2 + 1u;
    tf_round(x0,x1,17); tf_round(x0,x1,29); tf_round(x0,x1,16); tf_round(x0,x1,24);
    x0 += k2; x1 += k0 + 2u;
    tf_round(x0,x1,13); tf_round(x0,x1,15); tf_round(x0,x1,26); tf_round(x0,x1,6);
    x0 += k0; x1 += k1 + 3u;
    tf_round(x0,x1,17); tf_round(x0,x1,29); tf_round(x0,x1,16); tf_round(x0,x1,24);
    x0 += k1; x1 += k2 + 4u;
    tf_round(x0,x1,13); tf_round(x0,x1,15); tf_round(x0,x1,26); tf_round(x0,x1,6);
    x0 += k2; x1 += k0 + 5u;
    return make_uint2(x0, x1);
}
__device__ __forceinline__ float gumbel_at(int lin) {
    uint2 r = threefry01(0u, (uint32_t)lin);
    uint32_t bits = r.x ^ r.y;
    float f = __uint_as_float((bits >> 9) | 0x3F800000u) - 1.0f;
    float u = fmaxf(1.17549435e-38f, f);
    return -__logf(-__logf(u));
}

// ------------------------------- key helpers -------------------------------
__device__ __forceinline__ uint32_t f2key(float f) {
    uint32_t u = __float_as_uint(f);
    return (u & 0x80000000u) ? ~u : (u | 0x80000000u);
}
__device__ __forceinline__ float key2f(uint32_t k) {
    uint32_t fb = (k & 0x80000000u) ? (k ^ 0x80000000u) : ~k;
    return __uint_as_float(fb);
}

__device__ __forceinline__ float warp_sum(float v) {
    #pragma unroll
    for (int o = 16; o > 0; o >>= 1) v += __shfl_xor_sync(0xFFFFFFFFu, v, o);
    return v;
}

// ------------------------------- the kernel --------------------------------
__global__ __launch_bounds__(256, 7) void k_row(const float* __restrict__ pred,
                                                const float* __restrict__ truth,
                                                const int*   __restrict__ item_groups,
                                                const int*   __restrict__ user_groups,
                                                float* __restrict__ out) {
    __shared__ __align__(16) unsigned long long cand[jme::CAND];   // 2 KB
    __shared__ float sval[jme::TOPK];
    __shared__ int   s_ig[jme::TOPK];
    __shared__ __align__(16) float nz[jme::NS][jme::TOPK];   // noisy * 5
    __shared__ float expo_sb[jme::NTASK];            // aliased: hist
    __shared__ __align__(16) float sdelta[jme::TOPK];
    __shared__ float s_wred[8];                      // warp partials
    __shared__ int s_cnt;
    __shared__ uint32_t s_prefix;
    __shared__ int s_rem;
    __shared__ int s_ticket;
    uint32_t* hist = (uint32_t*)expo_sb;             // fallback alias

    const int row = blockIdx.x, tid = threadIdx.x;
    const int wid = tid >> 5, lane = tid & 31;
    const float4* rp4 = (const float4*)(pred  + (size_t)row * jme::NITEMS);
    const float4* tr4 = (const float4*)(truth + (size_t)row * jme::NITEMS);
    constexpr int N4 = jme::NITEMS / 4;              // 2500

    // task mapping for this thread (4 tasks tk = tid + 256*m, tk < 1000)
    int sI[4], iI[4];
    #pragma unroll
    for (int m = 0; m < 4; ++m) {
        int tk = tid + 256 * m;
        int s = (tk < jme::NTASK) ? (tk / jme::TOPK) : 0;
        sI[m] = s;
        iI[m] = (tk < jme::NTASK) ? (tk - jme::TOPK * s) : 0;
    }

    // =============== phase A: top-100 gather (pred only) ===================
    cand[tid] = 0ULL;
    if (tid == 0) s_cnt = 0;
    __syncthreads();

    const float THR = 2.15f;   // N(0,1): E[count>THR]~158, sd~12.5 (cap 256)
    #pragma unroll 5
    for (int c = tid; c < N4; c += 256) {
        float4 v = rp4[c];
        float mx = fmaxf(fmaxf(v.x, v.y), fmaxf(v.z, v.w));
        if (mx > THR) {
            const float vv[4] = {v.x, v.y, v.z, v.w};
            #pragma unroll
            for (int e = 0; e < 4; ++e) {
                if (vv[e] > THR) {
                    int pos = atomicAdd(&s_cnt, 1);
                    if (pos < jme::CAND)
                        cand[pos] = (((unsigned long long)f2key(vv[e])) << 32)
                                  | (uint32_t)(0xFFFFFFFFu - (uint32_t)(4 * c + e));
                }
            }
        }
    }

    // ---- gumbel RNG in the load/barrier shadow (input-independent) --------
    float g4[4];
    #pragma unroll
    for (int m = 0; m < 4; ++m) {
        int lin = (sI[m] * jme::B + row) * jme::TOPK + iI[m];
        g4[m] = gumbel_at(lin);
    }
    __syncthreads();

    // exact fallback (statistically never taken; correctness for any input)
    if (s_cnt < jme::TOPK || s_cnt > jme::CAND) {
        const float* rp = pred + (size_t)row * jme::NITEMS;
        if (tid == 0) { s_rem = jme::TOPK; s_prefix = 0u; }
        __syncthreads();
        uint32_t prefix = 0u;
        for (int shift = 24; shift >= 0; shift -= 8) {
            hist[tid] = 0u;
            __syncthreads();
            const uint32_t himask = (shift == 24) ? 0u : (0xFFFFFFFFu << (shift + 8));
            for (int i = tid; i < jme::NITEMS; i += 256) {
                uint32_t k = f2key(rp[i]);
                if ((k & himask) == prefix)
                    atomicAdd(&hist[(k >> shift) & 0xFF], 1u);
            }
            __syncthreads();
            if (tid == 0) {
                int cum = 0, sel = 0;
                for (int b = 255; b >= 0; --b) {
                    int h = (int)hist[b];
                    if (cum + h >= s_rem) { sel = b; s_rem -= cum; break; }
                    cum += h;
                }
                s_prefix = prefix | ((uint32_t)sel << shift);
            }
            __syncthreads();
            prefix = s_prefix;
            __syncthreads();
        }
        const uint32_t T = prefix;   // exact 100th-largest key
        cand[tid] = 0ULL;
        if (tid == 0) s_cnt = 0;
        __syncthreads();
        for (int i = tid; i < jme::NITEMS; i += 256) {
            uint32_t k = f2key(rp[i]);
            if (k >= T) {
                int pos = atomicAdd(&s_cnt, 1);
                if (pos < jme::CAND)
                    cand[pos] = (((unsigned long long)k) << 32)
                              | (uint32_t)(0xFFFFFFFFu - (uint32_t)i);
            }
        }
        __syncthreads();
    }

    // rank-by-count via LDS.128 pairs; zero-padding beyond s_cnt is neutral
    {
        const int n = (s_cnt < jme::CAND) ? s_cnt : jme::CAND;
        const int n2 = (n + 1) >> 1;
        const ulonglong2* c2 = (const ulonglong2*)cand;
        unsigned long long e = cand[tid];
        int r = 0;
        #pragma unroll 4
        for (int j = 0; j < n2; ++j) {
            ulonglong2 p = c2[j];
            r += (p.x > e) + (p.y > e);
        }
        if (e != 0ULL && r < jme::TOPK) {
            sval[r] = key2f((uint32_t)(e >> 32));
            s_ig[r] = item_groups[0xFFFFFFFFu - (uint32_t)e];
        }
    }
    __syncthreads();

    // =============== phase B: exposure (f32 tanh) + hidden truth loads =====
    #pragma unroll
    for (int m = 0; m < 4; ++m) {
        int tk = tid + 256 * m;
        if (tk < jme::NTASK)
            nz[sI[m]][iI[m]] = (sval[iI[m]] + g4[m]) * 5.0f;
    }
    __syncthreads();

    const float L2G = -0.3219280948873623f;     // log2(0.8)
    float tacc = 0.0f;                          // truth partial (hidden loads)
    #pragma unroll
    for (int m = 0; m < 4; ++m) {
        const int tk = tid + 256 * m;

        // ---- issue truth loads for this slice (consumed after tanh loop) --
        float4 p0 = tr4[tid + 256 * m];                      // c <= 1023
        float4 p1 = tr4[tid + 256 * (m + 4)];                // c <= 2047
        float4 p2 = make_float4(0.f, 0.f, 0.f, 0.f);
        if (m < 2) {
            int c2 = tid + 256 * (m + 8);
            if (c2 < N4) p2 = tr4[c2];                       // guard 2500
        }

        // ---- dense f32 tanh task (float4 smem reads) -----------------------
        if (tk < jme::NTASK) {
            const float4* rowp4 = (const float4*)nz[sI[m]];
            const float vi = nz[sI[m]][iI[m]];
            float t0 = 0.0f, t1 = 0.0f, t2 = 0.0f, t3 = 0.0f;
            #pragma unroll 5
            for (int q = 0; q < jme::TOPK / 4; ++q) {
                float4 vj = rowp4[q];
                float a0, a1, a2, a3;
                asm("tanh.approx.f32 %0, %1;" : "=f"(a0) : "f"(vi - vj.x));
                asm("tanh.approx.f32 %0, %1;" : "=f"(a1) : "f"(vi - vj.y));
                asm("tanh.approx.f32 %0, %1;" : "=f"(a2) : "f"(vi - vj.z));
                asm("tanh.approx.f32 %0, %1;" : "=f"(a3) : "f"(vi - vj.w));
                t0 += a0; t1 += a1; t2 += a2; t3 += a3;
            }
            float T = (t0 + t1) + (t2 + t3);
            float ex;
            asm("ex2.approx.f32 %0, %1;" : "=f"(ex)
                : "f"(fmaf(T, 0.5f * L2G, 49.5f * L2G)));
            expo_sb[tk] = ex;
        }

        // ---- consume truth loads (latency long gone) -----------------------
        tacc += ((p0.x + p0.y) + (p0.z + p0.w))
              + ((p1.x + p1.y) + (p1.z + p1.w))
              + ((p2.x + p2.y) + (p2.z + p2.w));
    }

    // truth reduce via warp shuffles (no expo_sb use; no barrier needed yet)
    {
        float w = warp_sum(tacc);
        if (lane == 0) s_wred[wid] = w;
    }
    __syncthreads();

    if (tid < jme::TOPK) {
        float acc = 0.0f;
        #pragma unroll
        for (int s = 0; s < jme::NS; ++s) acc += expo_sb[s * jme::TOPK + tid];
        sdelta[tid] = acc * 0.1f;           // raw e_i (t deferred)
    }
    if (tid == 0) {
        float ts = 0.0f;
        #pragma unroll
        for (int w = 0; w < 8; ++w) ts += s_wred[w];
        atomicAdd(&g_ts, (unsigned long long)__double2ll_rn((double)ts * 67108864.0));
    }
    __syncthreads();

    // =============== per-row partials -> global integer atomics ============
    if (tid == 1) {
        const float4* sd4 = (const float4*)sdelta;
        float sq = 0.0f, sl = 0.0f;
        #pragma unroll
        for (int i = 0; i < jme::TOPK / 4; ++i) {
            float4 e = sd4[i];
            sq += e.x * e.x + e.y * e.y + e.z * e.z + e.w * e.w;
            sl += (e.x + e.y) + (e.z + e.w);
        }
        atomicAdd(&g_sq, (unsigned long long)__double2ll_rn((double)sq * 4294967296.0));
        atomicAdd(&g_sl, (unsigned long long)__double2ll_rn((double)sl * 4294967296.0));
    }
    if (tid >= 32 && tid < 32 + jme::NIG) {
        const int g = tid - 32;
        float sD = 0.0f, c = 0.0f;
        for (int i = 0; i < jme::TOPK; ++i)
            if (s_ig[i] == g) { sD += sdelta[i]; c += 1.0f; }
        const int ug = user_groups[row];
        atomicAdd(&g_pairD[ug * jme::NIG + g],
                  (unsigned long long)__double2ll_rn((double)sD * 4294967296.0));
        atomicAdd(&g_pairC[ug * jme::NIG + g], (unsigned int)c);
    }

    // =============== last-block ticket: finalize ============================
    __threadfence();
    __syncthreads();
    if (tid == 0) s_ticket = (int)atomicAdd(&g_done, 1u);
    __syncthreads();
    if (s_ticket == jme::B - 1) {
        const double t = (double)(long long)__ldcg((const long long*)&g_ts)
                         / 67108864.0 / (double)(jme::B * jme::NITEMS);
        float a2 = 0.0f;
        if (tid < jme::NPAIR) {
            double D = (double)(long long)__ldcg((const long long*)&g_pairD[tid])
                       / 4294967296.0;
            double C = (double)__ldcg((const unsigned int*)&g_pairC[tid]);
            double avg = (C > 0.0) ? ((D - t * C) / fmax(C, 1.0)) : 0.0;
            a2 = (float)(avg * avg);
        }
        // shuffle-reduce the 128 pair squares (warps 0-3), fixed order
        float w = warp_sum(a2);
        if (lane == 0) s_wred[wid] = w;
        __syncthreads();
        if (tid == 0) {
            float gsum = s_wred[0] + s_wred[1] + s_wred[2] + s_wred[3];
            const double BK = (double)(jme::B * jme::TOPK);
            double Sq = (double)(long long)__ldcg((const long long*)&g_sq) / 4294967296.0;
            double Sl = (double)(long long)__ldcg((const long long*)&g_sl) / 4294967296.0;
            const float ii = (float)((Sq - 2.0 * t * Sl + BK * t * t) / BK);
            const float gg = gsum / (float)jme::NPAIR;
            out[0] = ii + gg;
            out[1] = ii;
            out[2] = gg;
        }
        // reset accumulators for next graph replay
        if (tid < jme::NPAIR) {
            atomicExch(&g_pairD[tid], 0ULL);
            atomicExch(&g_pairC[tid], 0u);
        }
        if (tid == 0) {
            atomicExch(&g_sq, 0ULL);
            atomicExch(&g_sl, 0ULL);
            atomicExch(&g_ts, 0ULL);
            atomicExch(&g_done, 0u);
        }
    }
}

// ------------------------------- launch ------------------------------------
extern "C" void kernel_launch(void* const* d_in, const int* in_sizes, int n_in,
                              void* d_out, int out_size) {
    const float* pred  = (const float*)d_in[0];
    const float* truth = (const float*)d_in[1];
    const int*   ug    = (const int*)  d_in[2];
    const int*   ig    = (const int*)  d_in[3];
    float* out = (float*)d_out;

    k_row<<<jme::B, 256>>>(pred, truth, ig, ug, out);
}

// round 14
// speedup vs baseline: 1.0092x; 1.0035x over previous
#include <cuda_runtime.h>
#include <stdint.h>

// ============================================================================
// JMEFairnessLoss — SINGLE kernel:
//   phase A: threshold top-100 gather on pred (fmax-prefiltered; exact radix
//            fallback); gumbel RNG hoisted into the load/barrier shadow
//   phase B: gumbel soft-rank exposure, f32 tanh (MUFU wall ~23us),
//            truth loads interleaved under the tanh shadow
//   rank-by-count via LDS.128 pairs, dynamic bound (s_cnt ~158)
//   epilogue: warp-shuffle reductions + fixed-point integer atomics
//             (deterministic) + last-block ticket finalize; self-reset.
//   Round 14: 8 CTAs/SM co-residency (regs=32 exactly fills the RF).
// ============================================================================

namespace jme {
constexpr int B      = 1024;
constexpr int NITEMS = 10000;
constexpr int TOPK   = 100;
constexpr int NS     = 10;
constexpr int NIG    = 16;
constexpr int NPAIR  = 128;
constexpr int NTASK  = NS * TOPK;     // 1000
constexpr int CAND   = 256;
}

// ---- global accumulators (all raw sums are >= 0; fixed-point, exact) ------
__device__ unsigned long long g_pairD[jme::NPAIR];   // sum e  * 2^32 per (ug,ig)
__device__ unsigned int       g_pairC[jme::NPAIR];   // counts (exact ints)
__device__ unsigned long long g_sq;                  // sum e^2 * 2^32
__device__ unsigned long long g_sl;                  // sum e   * 2^32
__device__ unsigned long long g_ts;                  // sum truth * 2^26
__device__ unsigned int       g_done;

// ------------------------------- threefry2x32 (JAX-exact, key=(0,1)) -------
__device__ __forceinline__ void tf_round(uint32_t& x0, uint32_t& x1, int r) {
    x0 += x1;
    x1 = __funnelshift_l(x1, x1, r);
    x1 ^= x0;
}
__device__ __forceinline__ uint2 threefry01(uint32_t x0, uint32_t x1) {
    const uint32_t k0 = 0u, k1 = 1u, k2 = 0x1BD11BDBu;
    x0 += k0; x1 += k1;
    tf_round(x0,x1,13); tf_round(x0,x1,15); tf_round(x0,x1,26); tf_round(x0,x1,6);
    x0 += k1; x1 += k2 + 1u;
    tf_round(x0,x1,17); tf_round(x0,x1,29); tf_round(x0,x1,16); tf_round(x0,x1,24);
    x0 += k2; x1 += k0 + 2u;
    tf_round(x0,x1,13); tf_round(x0,x1,15); tf_round(x0,x1,26); tf_round(x0,x1,6);
    x0 += k0; x1 += k1 + 3u;
    tf_round(x0,x1,17); tf_round(x0,x1,29); tf_round(x0,x1,16); tf_round(x0,x1,24);
    x0 += k1; x1 += k2 + 4u;
    tf_round(x0,x1,13); tf_round(x0,x1,15); tf_round(x0,x1,26); tf_round(x0,x1,6);
    x0 += k2; x1 += k0 + 5u;
    return make_uint2(x0, x1);
}
__device__ __forceinline__ float gumbel_at(int lin) {
    uint2 r = threefry01(0u, (uint32_t)lin);
    uint32_t bits = r.x ^ r.y;
    float f = __uint_as_float((bits >> 9) | 0x3F800000u) - 1.0f;
    float u = fmaxf(1.17549435e-38f, f);
    return -__logf(-__logf(u));
}

// ------------------------------- key helpers -------------------------------
__device__ __forceinline__ uint32_t f2key(float f) {
    uint32_t u = __float_as_uint(f);
    return (u & 0x80000000u) ? ~u : (u | 0x80000000u);
}
__device__ __forceinline__ float key2f(uint32_t k) {
    uint32_t fb = (k & 0x80000000u) ? (k ^ 0x80000000u) : ~k;
    return __uint_as_float(fb);
}

__device__ __forceinline__ float warp_sum(float v) {
    #pragma unroll
    for (int o = 16; o > 0; o >>= 1) v += __shfl_xor_sync(0xFFFFFFFFu, v, o);
    return v;
}

// ------------------------------- the kernel --------------------------------
__global__ __launch_bounds__(256, 8) void k_row(const float* __restrict__ pred,
                                                const float* __restrict__ truth,
                                                const int*   __restrict__ item_groups,
                                                const int*   __restrict__ user_groups,
                                                float* __restrict__ out) {
    __shared__ __align__(16) unsigned long long cand[jme::CAND];   // 2 KB
    __shared__ float sval[jme::TOPK];
    __shared__ int   s_ig[jme::TOPK];
    __shared__ __align__(16) float nz[jme::NS][jme::TOPK];   // noisy * 5
    __shared__ float expo_sb[jme::NTASK];            // aliased: hist
    __shared__ __align__(16) float sdelta[jme::TOPK];
    __shared__ float s_wred[8];                      // warp partials
    __shared__ int s_cnt;
    __shared__ uint32_t s_prefix;
    __shared__ int s_rem;
    __shared__ int s_ticket;
    uint32_t* hist = (uint32_t*)expo_sb;             // fallback alias

    const int row = blockIdx.x, tid = threadIdx.x;
    const int wid = tid >> 5, lane = tid & 31;
    const float4* rp4 = (const float4*)(pred  + (size_t)row * jme::NITEMS);
    const float4* tr4 = (const float4*)(truth + (size_t)row * jme::NITEMS);
    constexpr int N4 = jme::NITEMS / 4;              // 2500

    // task mapping for this thread (4 tasks tk = tid + 256*m, tk < 1000)
    int sI[4], iI[4];
    #pragma unroll
    for (int m = 0; m < 4; ++m) {
        int tk = tid + 256 * m;
        int s = (tk < jme::NTASK) ? (tk / jme::TOPK) : 0;
        sI[m] = s;
        iI[m] = (tk < jme::NTASK) ? (tk - jme::TOPK * s) : 0;
    }

    // =============== phase A: top-100 gather (pred only) ===================
    cand[tid] = 0ULL;
    if (tid == 0) s_cnt = 0;
    __syncthreads();

    const float THR = 2.15f;   // N(0,1): E[count>THR]~158, sd~12.5 (cap 256)
    #pragma unroll 5
    for (int c = tid; c < N4; c += 256) {
        float4 v = rp4[c];
        float mx = fmaxf(fmaxf(v.x, v.y), fmaxf(v.z, v.w));
        if (mx > THR) {
            const float vv[4] = {v.x, v.y, v.z, v.w};
            #pragma unroll
            for (int e = 0; e < 4; ++e) {
                if (vv[e] > THR) {
                    int pos = atomicAdd(&s_cnt, 1);
                    if (pos < jme::CAND)
                        cand[pos] = (((unsigned long long)f2key(vv[e])) << 32)
                                  | (uint32_t)(0xFFFFFFFFu - (uint32_t)(4 * c + e));
                }
            }
        }
    }

    // ---- gumbel RNG in the load/barrier shadow (input-independent) --------
    float g4[4];
    #pragma unroll
    for (int m = 0; m < 4; ++m) {
        int lin = (sI[m] * jme::B + row) * jme::TOPK + iI[m];
        g4[m] = gumbel_at(lin);
    }
    __syncthreads();

    // exact fallback (statistically never taken; correctness for any input)
    if (s_cnt < jme::TOPK || s_cnt > jme::CAND) {
        const float* rp = pred + (size_t)row * jme::NITEMS;
        if (tid == 0) { s_rem = jme::TOPK; s_prefix = 0u; }
        __syncthreads();
        uint32_t prefix = 0u;
        for (int shift = 24; shift >= 0; shift -= 8) {
            hist[tid] = 0u;
            __syncthreads();
            const uint32_t himask = (shift == 24) ? 0u : (0xFFFFFFFFu << (shift + 8));
            for (int i = tid; i < jme::NITEMS; i += 256) {
                uint32_t k = f2key(rp[i]);
                if ((k & himask) == prefix)
                    atomicAdd(&hist[(k >> shift) & 0xFF], 1u);
            }
            __syncthreads();
            if (tid == 0) {
                int cum = 0, sel = 0;
                for (int b = 255; b >= 0; --b) {
                    int h = (int)hist[b];
                    if (cum + h >= s_rem) { sel = b; s_rem -= cum; break; }
                    cum += h;
                }
                s_prefix = prefix | ((uint32_t)sel << shift);
            }
            __syncthreads();
            prefix = s_prefix;
            __syncthreads();
        }
        const uint32_t T = prefix;   // exact 100th-largest key
        cand[tid] = 0ULL;
        if (tid == 0) s_cnt = 0;
        __syncthreads();
        for (int i = tid; i < jme::NITEMS; i += 256) {
            uint32_t k = f2key(rp[i]);
            if (k >= T) {
                int pos = atomicAdd(&s_cnt, 1);
                if (pos < jme::CAND)
                    cand[pos] = (((unsigned long long)k) << 32)
                              | (uint32_t)(0xFFFFFFFFu - (uint32_t)i);
            }
        }
        __syncthreads();
    }

    // rank-by-count via LDS.128 pairs; zero-padding beyond s_cnt is neutral
    {
        const int n = (s_cnt < jme::CAND) ? s_cnt : jme::CAND;
        const int n2 = (n + 1) >> 1;
        const ulonglong2* c2 = (const ulonglong2*)cand;
        unsigned long long e = cand[tid];
        int r = 0;
        #pragma unroll 4
        for (int j = 0; j < n2; ++j) {
            ulonglong2 p = c2[j];
            r += (p.x > e) + (p.y > e);
        }
        if (e != 0ULL && r < jme::TOPK) {
            sval[r] = key2f((uint32_t)(e >> 32));
            s_ig[r] = item_groups[0xFFFFFFFFu - (uint32_t)e];
        }
    }
    __syncthreads();

    // =============== phase B: exposure (f32 tanh) + hidden truth loads =====
    #pragma unroll
    for (int m = 0; m < 4; ++m) {
        int tk = tid + 256 * m;
        if (tk < jme::NTASK)
            nz[sI[m]][iI[m]] = (sval[iI[m]] + g4[m]) * 5.0f;
    }
    __syncthreads();

    const float L2G  = -0.3219280948873623f;    // log2(0.8)
    const float L2T  = -3.321928094887362f;     // log2(0.1)  (fold /10 mean)
    float tacc = 0.0f;                          // truth partial (hidden loads)
    #pragma unroll
    for (int m = 0; m < 4; ++m) {
        const int tk = tid + 256 * m;

        // ---- issue truth loads for this slice (consumed after tanh loop) --
        float4 p0 = tr4[tid + 256 * m];                      // c <= 1023
        float4 p1 = tr4[tid + 256 * (m + 4)];                // c <= 2047
        float4 p2 = make_float4(0.f, 0.f, 0.f, 0.f);
        if (m < 2) {
            int c2 = tid + 256 * (m + 8);
            if (c2 < N4) p2 = tr4[c2];                       // guard 2500
        }

        // ---- dense f32 tanh task (float4 smem reads) -----------------------
        if (tk < jme::NTASK) {
            const float4* rowp4 = (const float4*)nz[sI[m]];
            const float vi = nz[sI[m]][iI[m]];
            float t0 = 0.0f, t1 = 0.0f, t2 = 0.0f, t3 = 0.0f;
            #pragma unroll 5
            for (int q = 0; q < jme::TOPK / 4; ++q) {
                float4 vj = rowp4[q];
                float a0, a1, a2, a3;
                asm("tanh.approx.f32 %0, %1;" : "=f"(a0) : "f"(vi - vj.x));
                asm("tanh.approx.f32 %0, %1;" : "=f"(a1) : "f"(vi - vj.y));
                asm("tanh.approx.f32 %0, %1;" : "=f"(a2) : "f"(vi - vj.z));
                asm("tanh.approx.f32 %0, %1;" : "=f"(a3) : "f"(vi - vj.w));
                t0 += a0; t1 += a1; t2 += a2; t3 += a3;
            }
            float T = (t0 + t1) + (t2 + t3);
            float ex;   // exposure * 0.1 (mean fold): 2^(rank_m1*L2G + L2T)
            asm("ex2.approx.f32 %0, %1;" : "=f"(ex)
                : "f"(fmaf(T, 0.5f * L2G, 49.5f * L2G + L2T)));
            expo_sb[tk] = ex;
        }

        // ---- consume truth loads (latency long gone) -----------------------
        tacc += ((p0.x + p0.y) + (p0.z + p0.w))
              + ((p1.x + p1.y) + (p1.z + p1.w))
              + ((p2.x + p2.y) + (p2.z + p2.w));
    }

    // truth reduce via warp shuffles (no expo_sb use; no barrier needed yet)
    {
        float w = warp_sum(tacc);
        if (lane == 0) s_wred[wid] = w;
    }
    __syncthreads();

    if (tid < jme::TOPK) {
        float acc = 0.0f;
        #pragma unroll
        for (int s = 0; s < jme::NS; ++s) acc += expo_sb[s * jme::TOPK + tid];
        sdelta[tid] = acc;                  // raw e_i (mean folded; t deferred)
    }
    if (tid == 0) {
        float ts = 0.0f;
        #pragma unroll
        for (int w = 0; w < 8; ++w) ts += s_wred[w];
        atomicAdd(&g_ts, (unsigned long long)__double2ll_rn((double)ts * 67108864.0));
    }
    __syncthreads();

    // =============== per-row partials -> global integer atomics ============
    if (tid == 1) {
        const float4* sd4 = (const float4*)sdelta;
        float sq = 0.0f, sl = 0.0f;
        #pragma unroll
        for (int i = 0; i < jme::TOPK / 4; ++i) {
            float4 e = sd4[i];
            sq += e.x * e.x + e.y * e.y + e.z * e.z + e.w * e.w;
            sl += (e.x + e.y) + (e.z + e.w);
        }
        atomicAdd(&g_sq, (unsigned long long)__double2ll_rn((double)sq * 4294967296.0));
        atomicAdd(&g_sl, (unsigned long long)__double2ll_rn((double)sl * 4294967296.0));
    }
    if (tid >= 32 && tid < 32 + jme::NIG) {
        const int g = tid - 32;
        float sD = 0.0f, c = 0.0f;
        for (int i = 0; i < jme::TOPK; ++i)
            if (s_ig[i] == g) { sD += sdelta[i]; c += 1.0f; }
        const int ug = user_groups[row];
        atomicAdd(&g_pairD[ug * jme::NIG + g],
                  (unsigned long long)__double2ll_rn((double)sD * 4294967296.0));
        atomicAdd(&g_pairC[ug * jme::NIG + g], (unsigned int)c);
    }

    // =============== last-block ticket: finalize ============================
    __threadfence();
    __syncthreads();
    if (tid == 0) s_ticket = (int)atomicAdd(&g_done, 1u);
    __syncthreads();
    if (s_ticket == jme::B - 1) {
        const double t = (double)(long long)__ldcg((const long long*)&g_ts)
                         / 67108864.0 / (double)(jme::B * jme::NITEMS);
        float a2 = 0.0f;
        if (tid < jme::NPAIR) {
            double D = (double)(long long)__ldcg((const long long*)&g_pairD[tid])
                       / 4294967296.0;
            double C = (double)__ldcg((const unsigned int*)&g_pairC[tid]);
            double avg = (C > 0.0) ? ((D - t * C) / fmax(C, 1.0)) : 0.0;
            a2 = (float)(avg * avg);
        }
        // shuffle-reduce the 128 pair squares (warps 0-3), fixed order
        float w = warp_sum(a2);
        if (lane == 0) s_wred[wid] = w;
        __syncthreads();
        if (tid == 0) {
            float gsum = s_wred[0] + s_wred[1] + s_wred[2] + s_wred[3];
            const double BK = (double)(jme::B * jme::TOPK);
            double Sq = (double)(long long)__ldcg((const long long*)&g_sq) / 4294967296.0;
            double Sl = (double)(long long)__ldcg((const long long*)&g_sl) / 4294967296.0;
            const float ii = (float)((Sq - 2.0 * t * Sl + BK * t * t) / BK);
            const float gg = gsum / (float)jme::NPAIR;
            out[0] = ii + gg;
            out[1] = ii;
            out[2] = gg;
        }
        // reset accumulators for next graph replay
        if (tid < jme::NPAIR) {
            atomicExch(&g_pairD[tid], 0ULL);
            atomicExch(&g_pairC[tid], 0u);
        }
        if (tid == 0) {
            atomicExch(&g_sq, 0ULL);
            atomicExch(&g_sl, 0ULL);
            atomicExch(&g_ts, 0ULL);
            atomicExch(&g_done, 0u);
        }
    }
}

// ------------------------------- launch ------------------------------------
extern "C" void kernel_launch(void* const* d_in, const int* in_sizes, int n_in,
                              void* d_out, int out_size) {
    const float* pred  = (const float*)d_in[0];
    const float* truth = (const float*)d_in[1];
    const int*   ug    = (const int*)  d_in[2];
    const int*   ig    = (const int*)  d_in[3];
    float* out = (float*)d_out;

    k_row<<<jme::B, 256>>>(pred, truth, ig, ug, out);
}